// round 14
// baseline (speedup 1.0000x reference)
#include <cuda_runtime.h>
#include <math_constants.h>
#include <cstdint>

// Shapes: V=1024 fixed; B,L,T from in_sizes. Scratch for B<=64, T<=1024, S<=256.
#define VOCAB      1024
#define MAXB       64
#define MAXTP      1056          // padded T rows (T + 32 slack)
#define SP         256           // padded extended-state stride (>= S = 2L+1), 8 per lane
#define RING       32            // smem ring slots (rows): 4 groups of 8
#define FULLMASK   0xffffffffu

#define LOG2E_F 1.4426950408889634f
#define LN2_F   0.6931471805599453f

typedef unsigned long long ull;

static __device__ __forceinline__ float fex2(float x) {
    float y; asm("ex2.approx.f32 %0, %1;" : "=f"(y) : "f"(x)); return y;
}

#define CP16(sm, gp) \
    asm volatile("cp.async.cg.shared.global [%0], [%1], 16;" :: "r"(sm), "l"(gp))
#define CP_COMMIT() \
    asm volatile("cp.async.commit_group;" ::: "memory")

static __device__ __forceinline__ void st_rel_cta(unsigned int addr, int v) {
    asm volatile("st.release.cta.shared.u32 [%0], %1;" :: "r"(addr), "r"(v) : "memory");
}
static __device__ __forceinline__ int ld_acq_cta(unsigned int addr) {
    int v;
    asm volatile("ld.acquire.cta.shared.u32 %0, [%1];" : "=r"(v) : "r"(addr) : "memory");
    return v;
}

// Scratch: per-(b,t) extended-label PROBABILITIES (softmax, gathered), padded.
__device__ float g_p[(size_t)MAXB * MAXTP * SP];
__device__ float g_loss[MAXB];

// ---------------------------------------------------------------------------
// Pass 1: per-row softmax + gather. ONE WARP PER ROW (32 values/lane in
// registers, MLP=8), no SMEM, no CTA barriers. 8 rows per 256-thread CTA.
// (Exact R9 form — proven.)
// ---------------------------------------------------------------------------
__global__ void __launch_bounds__(256)
softmax_gather_kernel(const float* __restrict__ pred,
                      const int*   __restrict__ gt,
                      int NT, int T, int TP, int L, int S)
{
    const int row  = blockIdx.x * 8 + (threadIdx.x >> 5);
    if (row >= NT) return;
    const int lane = threadIdx.x & 31;
    const int b    = row / T;
    const int t    = row - b * T;

    const float* __restrict__ p = pred + (size_t)row * VOCAB;

    float4 v[8];
    #pragma unroll
    for (int k = 0; k < 8; k++)
        v[k] = *reinterpret_cast<const float4*>(p + lane * 4 + k * 128);

    float mx = -CUDART_INF_F;
    #pragma unroll
    for (int k = 0; k < 8; k++)
        mx = fmaxf(mx, fmaxf(fmaxf(v[k].x, v[k].y), fmaxf(v[k].z, v[k].w)));
    #pragma unroll
    for (int o = 16; o; o >>= 1)
        mx = fmaxf(mx, __shfl_xor_sync(FULLMASK, mx, o));
    const float c = mx * LOG2E_F;

    float sum = 0.f;
    #pragma unroll
    for (int k = 0; k < 8; k++) {
        sum += fex2(fmaf(v[k].x, LOG2E_F, -c)) + fex2(fmaf(v[k].y, LOG2E_F, -c))
             + fex2(fmaf(v[k].z, LOG2E_F, -c)) + fex2(fmaf(v[k].w, LOG2E_F, -c));
    }
    #pragma unroll
    for (int o = 16; o; o >>= 1)
        sum += __shfl_xor_sync(FULLMASK, sum, o);
    const float inv = __frcp_rn(sum);

    float* __restrict__ out = g_p + ((size_t)b * TP + t) * SP;
    const int* __restrict__ gtb = gt + (size_t)b * L;
    float val[8];
    #pragma unroll
    for (int j = 0; j < 8; j++) {
        int s = lane * 8 + j;
        float r = 0.f;
        if (s < S) {
            int lab = 0;
            if (s & 1) {
                int idx = (s >> 1); if (idx > L - 1) idx = L - 1;
                lab = gtb[idx];
            }
            r = fex2(fmaf(__ldg(p + lab), LOG2E_F, -c)) * inv;
        }
        val[j] = r;
    }
    *reinterpret_cast<float4*>(out + lane * 8)     = make_float4(val[0], val[1], val[2], val[3]);
    *reinterpret_cast<float4*>(out + lane * 8 + 4) = make_float4(val[4], val[5], val[6], val[7]);
}

// ---------------------------------------------------------------------------
// Pass 2: CTC forward recursion, WARP-SPECIALIZED.
//   warp 0 (SMSP 0): consumer — pure scan (LDS + SHFL + FMA), R9 math.
//   warp 1 (SMSP 1): producer — cp.async ring fills, group (8 rows) at a time.
// Sync: smem flags with st.release.cta / ld.acquire.cta. 4-group ring (32KB),
// producer throttled to <= 3 groups ahead of the consumer.
// ---------------------------------------------------------------------------
__global__ void __launch_bounds__(64)
ctc_forward_kernel(const int* __restrict__ plen,
                   const int* __restrict__ gt,
                   const int* __restrict__ gtl,
                   int B, int T, int TP, int L, int S)
{
    __shared__ float ring[RING][SP];     // 32 KB
    __shared__ int   s_prod;             // groups fully landed in smem
    __shared__ int   s_cons;             // groups fully consumed

    const int b    = blockIdx.x;
    const int tid  = threadIdx.x;
    const int lane = tid & 31;
    const int wid  = tid >> 5;
    const int ilen = min(plen[b], T);
    const int tl   = gtl[b];
    const int nsteps = ilen - 1;                 // steps t = 1..nsteps
    const int ngrp   = (nsteps >> 3) + 1;        // groups of rows needed

    if (tid == 0) { s_prod = 0; s_cons = 0; }
    __syncthreads();

    const unsigned int prod_s =
        (unsigned int)__cvta_generic_to_shared(&s_prod);
    const unsigned int cons_s =
        (unsigned int)__cvta_generic_to_shared(&s_cons);

    // ======================= PRODUCER (warp 1) =======================
    if (wid == 1) {
        const float* gbase = g_p + (size_t)b * TP * SP + lane * 8;
        const unsigned int rb =
            (unsigned int)__cvta_generic_to_shared(ring) + (unsigned int)(lane * 32);
        for (int g = 0; g < ngrp; g++) {
            if (g >= 4) {                         // don't overwrite live group
                while (g >= ld_acq_cta(cons_s) + 4) { }
            }
            const float* gp = gbase + (size_t)(g * 8) * SP;
            #pragma unroll
            for (int r = 0; r < 8; r++) {
                unsigned int sa = rb + (unsigned int)((((g * 8 + r) & (RING - 1))) * (SP * 4));
                CP16(sa, gp); CP16(sa + 16, gp + 4);
                gp += SP;
            }
            CP_COMMIT();
            if (g >= 2) {                         // group g-2 has landed
                asm volatile("cp.async.wait_group 2;" ::: "memory");
                __syncwarp();
                if (lane == 0) st_rel_cta(prod_s, g - 1);
            }
        }
        asm volatile("cp.async.wait_all;" ::: "memory");
        __syncwarp();
        if (lane == 0) st_rel_cta(prod_s, ngrp);
        return;
    }

    // ======================= CONSUMER (warp 0) =======================
    const int* __restrict__ gtb = gt + (size_t)b * L;

    // Skip masks for the 4 odd (label) states only; even states never skip.
    float m1, m3, m5, m7;
    {
        float mm[4];
        #pragma unroll
        for (int jj = 0; jj < 4; jj++) {
            int s = lane * 8 + 2 * jj + 1;
            float v = 0.f;
            if (s >= 2 && s < S) {
                int lab = gtb[s >> 1], lm2 = gtb[(s >> 1) - 1];
                v = (lab != 0 && lab != lm2) ? 1.f : 0.f;
            }
            mm[jj] = v;
        }
        m1 = mm[0]; m3 = mm[1]; m5 = mm[2]; m7 = mm[3];
    }

    int   El = 0;
    float f  = (lane == 0) ? 0.f : 1.f;
    float a[8];
    #pragma unroll
    for (int j = 0; j < 8; j++) a[j] = 0.f;

#define WAITG(G) do { while (ld_acq_cta(prod_s) < (G) + 1) { } } while (0)

#define LDROW(Q0, Q1, R)                                                    \
    do {                                                                     \
        const float4* sp_ = reinterpret_cast<const float4*>(                 \
            &ring[(R) & (RING - 1)][lane * 8]);                              \
        (Q0) = sp_[0]; (Q1) = sp_[1];                                        \
    } while (0)

#define CTC_STEP(Q0, Q1)                                                    \
    do {                                                                     \
        float u7  = __shfl_up_sync(FULLMASK, a[7], 1);                       \
        float u7f = u7 * f;                                                  \
        float n0 = (a[0] + u7f)                * (Q0).x;                     \
        float n1 = fmaf(m1, u7f,  a[1] + a[0]) * (Q0).y;                     \
        float n2 = (a[2] + a[1])               * (Q0).z;                     \
        float n3 = fmaf(m3, a[1], a[3] + a[2]) * (Q0).w;                     \
        float n4 = (a[4] + a[3])               * (Q1).x;                     \
        float n5 = fmaf(m5, a[3], a[5] + a[4]) * (Q1).y;                     \
        float n6 = (a[6] + a[5])               * (Q1).z;                     \
        float n7 = fmaf(m7, a[5], a[7] + a[6]) * (Q1).w;                     \
        a[0]=n0; a[1]=n1; a[2]=n2; a[3]=n3; a[4]=n4; a[5]=n5; a[6]=n6; a[7]=n7; \
    } while (0)

#define CTC_RENORM()                                                        \
    do {                                                                     \
        float mx = fmaxf(fmaxf(fmaxf(a[0], a[1]), fmaxf(a[2], a[3])),       \
                         fmaxf(fmaxf(a[4], a[5]), fmaxf(a[6], a[7])));       \
        bool nz = (mx > 0.f);                                                \
        int  e  = nz ? ((__float_as_int(mx) >> 23) - 127) : 0;               \
        int  Elp = El + e;                                                   \
        int  Eleft = __shfl_up_sync(FULLMASK, Elp, 1);                       \
        if (!nz && lane > 0) Elp = Eleft;      /* adopt neighbor's scale */  \
        if (nz) {                                                            \
            float sc = __int_as_float((127 - e) << 23);                      \
            _Pragma("unroll")                                                \
            for (int j = 0; j < 8; j++) a[j] *= sc;                          \
        }                                                                    \
        El = Elp;                                                            \
        int El2 = __shfl_up_sync(FULLMASK, El, 1);                           \
        int dE  = El2 - El;                                                  \
        if (lane == 0 || dE < -126) f = 0.f;                                 \
        else f = __int_as_float((min(dE, 126) + 127) << 23);                 \
    } while (0)

    float4 q0, q1;

    // Group 0: alpha(t=0) from row 0, then steps t = 1..min(7, nsteps).
    WAITG(0);
    LDROW(q0, q1, 0);
    if (lane == 0) {
        a[0] = q0.x;
        a[1] = (tl > 0) ? q0.y : 0.f;
    }
    {
        int tlim0 = min(7, nsteps);
        if (nsteps >= 1) LDROW(q0, q1, 1);
        for (int t = 1; t <= tlim0; t++) {
            float4 nq0 = q0, nq1 = q1;
            if (t < 7) LDROW(nq0, nq1, t + 1);   // rows <= 7: same group
            CTC_STEP(q0, q1);
            q0 = nq0; q1 = nq1;
        }
        if (tlim0 == 7) CTC_RENORM();
    }

    // Full groups: g covers steps t = 8g .. 8g+7.
    int g = 1;
    for (; 8 * g + 7 <= nsteps; g++) {
        WAITG(g);
        if (lane == 0) st_rel_cta(cons_s, g);    // groups 0..g-1 consumed
        LDROW(q0, q1, 8 * g);
        #pragma unroll
        for (int k = 0; k < 8; k++) {
            float4 nq0 = q0, nq1 = q1;
            if (k < 7) LDROW(nq0, nq1, 8 * g + k + 1);
            CTC_STEP(q0, q1);
            if (k == 7) CTC_RENORM();
            q0 = nq0; q1 = nq1;
        }
    }
    // Tail: remaining steps all inside group g.
    {
        int t = 8 * g;
        if (t <= nsteps) {
            WAITG(g);
            if (lane == 0) st_rel_cta(cons_s, g);
            LDROW(q0, q1, t);
            for (; t <= nsteps; t++) {
                float4 nq0 = q0, nq1 = q1;
                if (t + 1 <= nsteps) LDROW(nq0, nq1, t + 1);
                CTC_STEP(q0, q1);
                q0 = nq0; q1 = nq1;
            }
        }
    }
    if (lane == 0) st_rel_cta(cons_s, 1 << 30);  // release producer throttle
#undef CTC_STEP
#undef CTC_RENORM
#undef WAITG
#undef LDROW

    // end_ll over alpha[2*tl] and alpha[max(2*tl-1,0)]
    int s1 = 2 * tl;
    int s2 = (2 * tl - 1 > 0) ? (2 * tl - 1) : 0;
    int lane1 = s1 >> 3, slot1 = s1 & 7;
    int lane2 = s2 >> 3, slot2 = s2 & 7;
    float v1 = a[0], v2 = a[0];
    #pragma unroll
    for (int j = 1; j < 8; j++) { v1 = (slot1 == j) ? a[j] : v1;
                                  v2 = (slot2 == j) ? a[j] : v2; }
    int   E1 = __shfl_sync(FULLMASK, El, lane1);
    int   E2 = __shfl_sync(FULLMASK, El, lane2);
    v1 = __shfl_sync(FULLMASK, v1, lane1);
    v2 = __shfl_sync(FULLMASK, v2, lane2);

    if (lane == 0) {
        float l1 = (v1 > 0.f) ? (log2f(v1) + (float)E1) : -3.0e38f;
        float l2 = (v2 > 0.f) ? (log2f(v2) + (float)E2) : -3.0e38f;
        float mx = fmaxf(l1, l2);
        float loss;
        if (mx < -2.0e38f) {
            loss = 0.f;                    // zero_infinity: p == 0
        } else {
            float tot2 = mx + log2f(exp2f(l1 - mx) + exp2f(l2 - mx));
            loss = -tot2 * LN2_F;
        }
        g_loss[b] = loss / (float)tl;
    }
}

// ---------------------------------------------------------------------------
// Pass 3: deterministic batch-mean reduction (single warp).
// ---------------------------------------------------------------------------
__global__ void reduce_loss_kernel(float* __restrict__ out, int B)
{
    float v = 0.f;
    for (int i = threadIdx.x; i < B; i += 32) v += g_loss[i];
    #pragma unroll
    for (int o = 16; o; o >>= 1) v += __shfl_xor_sync(FULLMASK, v, o);
    if (threadIdx.x == 0) out[0] = v / (float)B;
}

// ---------------------------------------------------------------------------
extern "C" void kernel_launch(void* const* d_in, const int* in_sizes, int n_in,
                              void* d_out, int out_size)
{
    const float* pred = (const float*)d_in[0];
    const int*   plen = (const int*)d_in[1];
    const int*   gt   = (const int*)d_in[2];
    const int*   gtl  = (const int*)d_in[3];

    const int B  = in_sizes[1];
    const int L  = in_sizes[2] / B;
    const int T  = in_sizes[0] / (B * VOCAB);
    const int S  = 2 * L + 1;
    const int TP = T + 32;                // padded rows (fill slack)
    const int NT = B * T;

    softmax_gather_kernel<<<(NT + 7) / 8, 256>>>(pred, gt, NT, T, TP, L, S);
    ctc_forward_kernel<<<B, 64>>>(plen, gt, gtl, B, T, TP, L, S);
    reduce_loss_kernel<<<1, 32>>>((float*)d_out, B);
}

// round 16
// speedup vs baseline: 1.2066x; 1.2066x over previous
#include <cuda_runtime.h>
#include <math_constants.h>
#include <cstdint>

// Shapes: V=1024 fixed; B,L,T from in_sizes. Scratch for B<=64, T<=1024, S<=256.
#define VOCAB      1024
#define MAXB       64
#define MAXTP      1056          // padded T rows (T + 32 prefetch slack)
#define SPC        128           // compact row: [0]=blank, [4+i]=label i (i<L), pad 0
#define RING       32            // smem ring slots (rows) per warp
#define DIST       28            // prefetch distance (rows ahead)
#define FULLMASK   0xffffffffu

#define LOG2E_F 1.4426950408889634f
#define LN2_F   0.6931471805599453f

typedef unsigned long long ull;

static __device__ __forceinline__ float fex2(float x) {
    float y; asm("ex2.approx.f32 %0, %1;" : "=f"(y) : "f"(x)); return y;
}

#define CP16(sm, gp) \
    asm volatile("cp.async.cg.shared.global [%0], [%1], 16;" :: "r"(sm), "l"(gp))
#define CP_COMMIT() \
    asm volatile("cp.async.commit_group;" ::: "memory")
#define CP_WAIT_26() \
    asm volatile("cp.async.wait_group 26;" ::: "memory")
#define CP_WAIT_27() \
    asm volatile("cp.async.wait_group 27;" ::: "memory")
#define CP_WAIT_ALL() \
    asm volatile("cp.async.wait_all;" ::: "memory")

// Scratch: compact per-(b,t) probability rows (blank + L labels), padded.
__device__ float g_p[(size_t)MAXB * MAXTP * SPC];
__device__ float g_loss[MAXB];

// ---------------------------------------------------------------------------
// Pass 1: per-row softmax + COMPACT gather. ONE WARP PER ROW (32 values/lane
// in registers, MLP=8). Row output: 512B = [blank, 0,0,0, lab0..lab99, 0...].
// Lanes 0..24 write 4 label probs each; lanes 25..30 write zero pads;
// lane 31 writes the blank scalar. One 16B store per lane.
// ---------------------------------------------------------------------------
__global__ void __launch_bounds__(256)
softmax_gather_kernel(const float* __restrict__ pred,
                      const int*   __restrict__ gt,
                      int NT, int T, int TP, int L)
{
    const int row  = blockIdx.x * 8 + (threadIdx.x >> 5);
    if (row >= NT) return;
    const int lane = threadIdx.x & 31;
    const int b    = row / T;
    const int t    = row - b * T;

    const float* __restrict__ p = pred + (size_t)row * VOCAB;

    float4 v[8];
    #pragma unroll
    for (int k = 0; k < 8; k++)
        v[k] = *reinterpret_cast<const float4*>(p + lane * 4 + k * 128);

    float mx = -CUDART_INF_F;
    #pragma unroll
    for (int k = 0; k < 8; k++)
        mx = fmaxf(mx, fmaxf(fmaxf(v[k].x, v[k].y), fmaxf(v[k].z, v[k].w)));
    #pragma unroll
    for (int o = 16; o; o >>= 1)
        mx = fmaxf(mx, __shfl_xor_sync(FULLMASK, mx, o));
    const float c = mx * LOG2E_F;

    float sum = 0.f;
    #pragma unroll
    for (int k = 0; k < 8; k++) {
        sum += fex2(fmaf(v[k].x, LOG2E_F, -c)) + fex2(fmaf(v[k].y, LOG2E_F, -c))
             + fex2(fmaf(v[k].z, LOG2E_F, -c)) + fex2(fmaf(v[k].w, LOG2E_F, -c));
    }
    #pragma unroll
    for (int o = 16; o; o >>= 1)
        sum += __shfl_xor_sync(FULLMASK, sum, o);
    const float inv = __frcp_rn(sum);

    float* __restrict__ out = g_p + ((size_t)b * TP + t) * SPC;
    const int* __restrict__ gtb = gt + (size_t)b * L;

    float4 w = make_float4(0.f, 0.f, 0.f, 0.f);
    int ofs;
    if (lane < 25) {
        // labels 4*lane .. 4*lane+3 (lane 24 covers 96..99; L=100)
        ofs = 4 + 4 * lane;
        #pragma unroll
        for (int k = 0; k < 4; k++) {
            int j = 4 * lane + k;
            float r = 0.f;
            if (j < L) {
                int lab = gtb[j];
                r = fex2(fmaf(__ldg(p + lab), LOG2E_F, -c)) * inv;
            }
            (&w.x)[k] = r;
        }
    } else if (lane < 31) {
        ofs = 4 + 4 * lane;                 // zero pads 104..127
    } else {
        ofs = 0;                            // blank scalar in .x
        w.x = fex2(fmaf(__ldg(p), LOG2E_F, -c)) * inv;
    }
    *reinterpret_cast<float4*>(out + ofs) = w;
}

// ---------------------------------------------------------------------------
// Pass 2: CTC forward recursion, prob domain, PER-LANE block floating point,
// renorm every 8 steps (R9 math, proven). One warp per CTA/batch; lane l owns
// states [8l, 8l+7]. COMPACT rows: even states use the broadcast blank scalar
// (row[0]); odd states use the contiguous label float4 (row[4+4l]). One CP16
// per lane per row fill (512B rows), halving the LDGSTS issue tax.
// Lane 31's label offset is clamped to 124 (zero pads) — its states are all
// >= S and must see zero probs, and 4+4*31 would run past the row.
// ---------------------------------------------------------------------------
__global__ void __launch_bounds__(32)
ctc_forward_kernel(const int* __restrict__ plen,
                   const int* __restrict__ gt,
                   const int* __restrict__ gtl,
                   int B, int T, int TP, int L, int S)
{
    __shared__ float ring[RING][SPC];     // 16 KB

    const int b    = blockIdx.x;
    const int lane = threadIdx.x;
    const int ilen = min(plen[b], T);
    const int tl   = gtl[b];
    const float* __restrict__ Pb = g_p + (size_t)b * TP * SPC;   // row base
    const int* __restrict__ gtb = gt + (size_t)b * L;
    const unsigned int rb =
        (unsigned int)__cvta_generic_to_shared(ring) + (unsigned int)(lane * 16);
    const int lv_ofs = (lane < 31) ? (4 + 4 * lane) : 124;   // lane31 -> zero pads

    // Skip masks for the 4 odd (label) states only; even states never skip.
    float m1, m3, m5, m7;
    {
        float mm[4];
        #pragma unroll
        for (int jj = 0; jj < 4; jj++) {
            int s = lane * 8 + 2 * jj + 1;
            float v = 0.f;
            if (s >= 2 && s < S) {
                int lab = gtb[s >> 1], lm2 = gtb[(s >> 1) - 1];
                v = (lab != 0 && lab != lm2) ? 1.f : 0.f;
            }
            mm[jj] = v;
        }
        m1 = mm[0]; m3 = mm[1]; m5 = mm[2]; m7 = mm[3];
    }

    // alpha(t=0): state 0 = blank (row[0]), state 1 = label 0 (row[4]).
    float a[8];
    #pragma unroll
    for (int j = 0; j < 8; j++) a[j] = 0.f;
    if (lane == 0) {
        a[0] = Pb[0];
        a[1] = (tl > 0) ? Pb[4] : 0.f;
    }

    int   El = 0;                          // per-lane exponent
    float f  = (lane == 0) ? 0.f : 1.f;    // 2^(El_left - El); lane 0 has no left
    const int nsteps = ilen - 1;           // recursion runs t = 1 .. ilen-1

    // LV = label float4 (odd states), PB = blank scalar (even states).
#define CTC_STEP(LV, PB)                                                    \
    do {                                                                     \
        float u7  = __shfl_up_sync(FULLMASK, a[7], 1);                       \
        float u7f = u7 * f;                                                  \
        float n0 = (a[0] + u7f)                * (PB);                       \
        float n1 = fmaf(m1, u7f,  a[1] + a[0]) * (LV).x;                     \
        float n2 = (a[2] + a[1])               * (PB);                       \
        float n3 = fmaf(m3, a[1], a[3] + a[2]) * (LV).y;                     \
        float n4 = (a[4] + a[3])               * (PB);                       \
        float n5 = fmaf(m5, a[3], a[5] + a[4]) * (LV).z;                     \
        float n6 = (a[6] + a[5])               * (PB);                       \
        float n7 = fmaf(m7, a[5], a[7] + a[6]) * (LV).w;                     \
        a[0]=n0; a[1]=n1; a[2]=n2; a[3]=n3; a[4]=n4; a[5]=n5; a[6]=n6; a[7]=n7; \
    } while (0)

#define CTC_RENORM()                                                        \
    do {                                                                     \
        float mx = fmaxf(fmaxf(fmaxf(a[0], a[1]), fmaxf(a[2], a[3])),       \
                         fmaxf(fmaxf(a[4], a[5]), fmaxf(a[6], a[7])));       \
        bool nz = (mx > 0.f);                                                \
        int  e  = nz ? ((__float_as_int(mx) >> 23) - 127) : 0;               \
        int  Elp = El + e;                                                   \
        int  Eleft = __shfl_up_sync(FULLMASK, Elp, 1);                       \
        if (!nz && lane > 0) Elp = Eleft;      /* adopt neighbor's scale */  \
        if (nz) {                                                            \
            float sc = __int_as_float((127 - e) << 23);                      \
            _Pragma("unroll")                                                \
            for (int j = 0; j < 8; j++) a[j] *= sc;                          \
        }                                                                    \
        El = Elp;                                                            \
        int El2 = __shfl_up_sync(FULLMASK, El, 1);                           \
        int dE  = El2 - El;                                                  \
        if (lane == 0 || dE < -126) f = 0.f;                                 \
        else f = __int_as_float((min(dE, 126) + 127) << 23);                 \
    } while (0)

    // Load labels + blank for row r from the ring.
#define LDROW(LV, PB, R)                                                    \
    do {                                                                     \
        const float* rp_ = &ring[(R) & (RING - 1)][0];                       \
        (LV) = *reinterpret_cast<const float4*>(rp_ + lv_ofs);               \
        (PB) = rp_[0];                                                       \
    } while (0)

    // Prologue: fill ring with rows 1..DIST (one 16B cp.async per lane).
    {
        const float* gp = Pb + SPC + lane * 4;     // row 1, lane's 16B
        #pragma unroll 4
        for (int r = 1; r <= DIST; r++) {
            unsigned int sa = rb + (unsigned int)((r & (RING - 1)) * (SPC * 4));
            CP16(sa, gp);
            CP_COMMIT();
            gp += SPC;
        }
    }

    float4 lv = make_float4(0.f, 0.f, 0.f, 0.f);
    float  pb = 0.f;
    if (nsteps >= 1) {
        CP_WAIT_27();                        // row 1 landed
        LDROW(lv, pb, 1);
    }

    const float* fill_ptr = Pb + (size_t)(1 + DIST) * SPC + lane * 4;
    int t = 1;
    for (; t + 7 <= nsteps; t += 8) {
        #pragma unroll
        for (int k = 0; k < 8; k++) {
            CP_WAIT_26();                    // row t+k+1 landed
            float4 nlv; float npb;
            LDROW(nlv, npb, t + k + 1);
            // refill: row t+k+DIST into its slot
            {
                unsigned int sa = rb +
                    (unsigned int)((((t + k + DIST) & (RING - 1))) * (SPC * 4));
                CP16(sa, fill_ptr + (size_t)k * SPC);
                CP_COMMIT();
            }
            CTC_STEP(lv, pb);
            if (k == 7) CTC_RENORM();
            lv = nlv; pb = npb;
        }
        fill_ptr += 8 * SPC;
    }
    // Tail: all remaining rows were prefetched into the ring already.
    if (t <= nsteps) {
        CP_WAIT_ALL();
        for (; t <= nsteps; t++) {
            CTC_STEP(lv, pb);
            LDROW(lv, pb, t + 1);            // contents unused past nsteps
        }
    }
#undef CTC_STEP
#undef CTC_RENORM
#undef LDROW

    // end_ll over alpha[2*tl] and alpha[max(2*tl-1,0)]
    int s1 = 2 * tl;
    int s2 = (2 * tl - 1 > 0) ? (2 * tl - 1) : 0;
    int lane1 = s1 >> 3, slot1 = s1 & 7;
    int lane2 = s2 >> 3, slot2 = s2 & 7;
    float v1 = a[0], v2 = a[0];
    #pragma unroll
    for (int j = 1; j < 8; j++) { v1 = (slot1 == j) ? a[j] : v1;
                                  v2 = (slot2 == j) ? a[j] : v2; }
    int   E1 = __shfl_sync(FULLMASK, El, lane1);
    int   E2 = __shfl_sync(FULLMASK, El, lane2);
    v1 = __shfl_sync(FULLMASK, v1, lane1);
    v2 = __shfl_sync(FULLMASK, v2, lane2);

    if (lane == 0) {
        float l1 = (v1 > 0.f) ? (log2f(v1) + (float)E1) : -3.0e38f;
        float l2 = (v2 > 0.f) ? (log2f(v2) + (float)E2) : -3.0e38f;
        float mx = fmaxf(l1, l2);
        float loss;
        if (mx < -2.0e38f) {
            loss = 0.f;                    // zero_infinity: p == 0
        } else {
            float tot2 = mx + log2f(exp2f(l1 - mx) + exp2f(l2 - mx));
            loss = -tot2 * LN2_F;
        }
        g_loss[b] = loss / (float)tl;
    }
}

// ---------------------------------------------------------------------------
// Pass 3: deterministic batch-mean reduction (single warp).
// ---------------------------------------------------------------------------
__global__ void reduce_loss_kernel(float* __restrict__ out, int B)
{
    float v = 0.f;
    for (int i = threadIdx.x; i < B; i += 32) v += g_loss[i];
    #pragma unroll
    for (int o = 16; o; o >>= 1) v += __shfl_xor_sync(FULLMASK, v, o);
    if (threadIdx.x == 0) out[0] = v / (float)B;
}

// ---------------------------------------------------------------------------
extern "C" void kernel_launch(void* const* d_in, const int* in_sizes, int n_in,
                              void* d_out, int out_size)
{
    const float* pred = (const float*)d_in[0];
    const int*   plen = (const int*)d_in[1];
    const int*   gt   = (const int*)d_in[2];
    const int*   gtl  = (const int*)d_in[3];

    const int B  = in_sizes[1];
    const int L  = in_sizes[2] / B;
    const int T  = in_sizes[0] / (B * VOCAB);
    const int S  = 2 * L + 1;
    const int TP = T + 32;                // padded rows (prefetch slack)
    const int NT = B * T;

    softmax_gather_kernel<<<(NT + 7) / 8, 256>>>(pred, gt, NT, T, TP, L);
    ctc_forward_kernel<<<B, 32>>>(plen, gt, gtl, B, T, TP, L, S);
    reduce_loss_kernel<<<1, 32>>>((float*)d_out, B);
}